// round 15
// baseline (speedup 1.0000x reference)
#include <cuda_runtime.h>

// Problem constants (B, S, K) = (512, 2048, 17)
#define BB 512
#define SS 2048
#define KK 17
#define SK (SS * KK)
#define CHUNKS 32
#define CL 64               // steps owned per chunk
#define WU 8                // warm-up steps
#define TSTEPS 16           // steps per emission tile
#define TILEF (TSTEPS * KK) // 272 floats per tile
#define SCAN_WPB 8
#define NCOPY_BLOCKS 512
#define NSCAN_BLOCKS ((BB * CHUNKS) / SCAN_WPB)   // 2048

__device__ float g_part2[BB * CHUNKS];   // per-(seq,chunk) loss contribution

__device__ __forceinline__ void cp16(void* smem, const void* gmem) {
    unsigned s = (unsigned)__cvta_generic_to_shared(smem);
    asm volatile("cp.async.cg.shared.global [%0], [%1], 16;\n" :: "r"(s), "l"(gmem));
}
#define CP_COMMIT() asm volatile("cp.async.commit_group;\n" ::: "memory")
#define CP_WAIT1()  asm volatile("cp.async.wait_group 1;\n" ::: "memory")
#define CP_WAIT0()  asm volatile("cp.async.wait_group 0;\n" ::: "memory")

// one 272-float tile (68 x 16B) global -> shared via cp.async
__device__ __forceinline__ void load_tile(float* dst, const float* src, int lane) {
    cp16(dst + lane * 4,        src + lane * 4);
    cp16(dst + (32 + lane) * 4, src + (32 + lane) * 4);
    if (lane < 4)
        cp16(dst + (64 + lane) * 4, src + (64 + lane) * 4);
}

// one unmasked forward step (all in-mask); renorm bookkeeping every 8 steps.
// NOTE: no __syncwarp — the warp is convergent here, and the STS->LDS pair on
// arow aliases (runtime lane index), so both the compiler and the in-order
// per-warp LSU path preserve the store->load dependency warp-wide.
#define STEP_ONCE(tt)                                                          \
    {                                                                          \
        float e = eb[(tt) * KK + lane];                                        \
        float gg = __expf(e);                                                  \
        arow[wid][lane] = a;                                                   \
        const float* ar = arow[wid];                                           \
        float4 v0 = *(const float4*)&ar[0];                                    \
        float4 v1 = *(const float4*)&ar[4];                                    \
        float4 v2 = *(const float4*)&ar[8];                                    \
        float4 v3 = *(const float4*)&ar[12];                                   \
        float  v16 = ar[16];                                                   \
        float s0 = v0.x * w[0];                                                \
        float s1 = v0.y * w[1];                                                \
        float s2 = v0.z * w[2];                                                \
        float s3 = v0.w * w[3];                                                \
        s0 = fmaf(v1.x, w[4],  s0);                                            \
        s1 = fmaf(v1.y, w[5],  s1);                                            \
        s2 = fmaf(v1.z, w[6],  s2);                                            \
        s3 = fmaf(v1.w, w[7],  s3);                                            \
        s0 = fmaf(v2.x, w[8],  s0);                                            \
        s1 = fmaf(v2.y, w[9],  s1);                                            \
        s2 = fmaf(v2.z, w[10], s2);                                            \
        s3 = fmaf(v2.w, w[11], s3);                                            \
        s0 = fmaf(v3.x, w[12], s0);                                            \
        s1 = fmaf(v3.y, w[13], s1);                                            \
        s2 = fmaf(v3.z, w[14], s2);                                            \
        s3 = fmaf(v3.w, w[15], s3);                                            \
        s0 = fmaf(v16,  w[16], s0);                                            \
        float s = (s0 + s1) + (s2 + s3);                                       \
        a = s * gg;                                                            \
        if (((tt) & 7) == 0) {                                                 \
            float m0 = fmaxf(fmaxf(v0.x, v0.y), fmaxf(v0.z, v0.w));            \
            float m1 = fmaxf(fmaxf(v1.x, v1.y), fmaxf(v1.z, v1.w));            \
            float m2 = fmaxf(fmaxf(v2.x, v2.y), fmaxf(v2.z, v2.w));            \
            float m3 = fmaxf(fmaxf(v3.x, v3.y), fmaxf(v3.z, v3.w));            \
            float mx = fmaxf(fmaxf(m0, m1), fmaxf(fmaxf(m2, m3), v16));        \
            int e2 = (__float_as_int(mx) >> 23) - 127;                         \
            float scale = __int_as_float((127 - e2) << 23);                    \
            a *= scale;                                                        \
            M += (float)e2 * 0.6931471805599453f;                              \
        }                                                                      \
    }

__global__ __launch_bounds__(256, 5) void crf_kernel(
    const float* __restrict__ em,      // [B,S,K]
    const float* __restrict__ startT,  // [K]
    const float* __restrict__ endT,    // [K]
    const float* __restrict__ trans,   // [K,K]
    const int*   __restrict__ labels,  // [B,S]
    const int*   __restrict__ attn,    // [B,S]
    float* __restrict__ out,           // [0]=loss, [1..]=emissions copy
    int copy_emissions)
{
    // ======== copy blocks LAST in the grid: scan is the long pole ========
    if (blockIdx.x >= NSCAN_BLOCKS) {
        if (!copy_emissions) return;
        const size_t base = (size_t)(blockIdx.x - NSCAN_BLOCKS) * SK;
        const float4* s4 = (const float4*)(em + base);
        float* dst = out + 1 + base;           // dst+3 is 16B-aligned
        const int n4 = (SK - 4) / 4;           // 8703 aligned float4 stores
        for (int j = threadIdx.x; j < n4; j += 256) {
            float4 x = s4[j];
            float4 y = s4[j + 1];              // overlapping load: L1 hit
            *(float4*)(dst + 3 + 4 * j) = make_float4(x.w, y.x, y.y, y.z);
        }
        if (threadIdx.x == 0) {
            float4 x0 = s4[0];
            dst[0] = x0.x; dst[1] = x0.y; dst[2] = x0.z;
            dst[SK - 1] = em[base + SK - 1];
        }
        return;
    }

    // ======== scan blocks: 8 warps, each = one (sequence, chunk) ========
    const int tid  = threadIdx.x;
    const int wid  = tid >> 5;
    const int lane = tid & 31;
    const int gw   = blockIdx.x * SCAN_WPB + wid;
    const int b    = gw / CHUNKS;
    const int c    = gw % CHUNKS;

    const float* emb = em + (size_t)b * SK;
    const int*   lab = labels + (size_t)b * SS;
    const int*   msk = attn   + (size_t)b * SS;

    __shared__ __align__(16) float ebuf[SCAN_WPB][2][TILEF];
    __shared__ __align__(16) float arow[SCAN_WPB][32];

    // ---- phase 1: masks + numerator for steps t in [c*CL, (c+1)*CL) ----
    const int tbase = c * CL;
    unsigned mwords[2];
    float numv = 0.0f;
    #pragma unroll
    for (int r = 0; r < 2; r++) {
        int t  = tbase + 32 * r + lane;
        int lt = lab[t];
        bool m = (msk[t] != 0) && (lt >= 0);
        mwords[r] = __ballot_sync(0xffffffffu, m);
        if (m && t > 0) {
            int lp  = lab[t - 1];
            int lpc = (lp < 0) ? 0 : lp;
            numv += __ldg(&trans[lpc * KK + lt]) + emb[t * KK + lt];
        }
    }
    #pragma unroll
    for (int o = 16; o; o >>= 1)
        numv += __shfl_xor_sync(0xffffffffu, numv, o);

    // active: chunk has any owned step in-mask (mask is a prefix)
    bool active = (c == 0) || ((mwords[0] & 1u) != 0);
    if (!active) {
        if (lane == 0) g_part2[gw] = 0.0f;
        return;
    }

    // does this chunk contain the global last masked index?
    bool mnext = false;
    if (c < CHUNKS - 1) {
        int t = (c + 1) * CL;
        mnext = (msk[t] != 0) && (lab[t] >= 0);
    }
    const bool contains = !mnext;

    if (contains) {   // numerator end term (uniform across lanes)
        int li;
        if (mwords[1]) li = tbase + 32 + (31 - __clz(mwords[1]));
        else           li = tbase +      (31 - __clz(mwords[0]));
        int ll = lab[li];
        numv += endT[(ll < 0) ? 0 : ll];
    }
    if (c == 0) {
        int l0  = lab[0];
        int l0c = (l0 < 0) ? 0 : l0;
        numv += startT[l0c] + emb[l0c];
    }

    // exp(transitions) column for this lane's state
    float w[KK];
    #pragma unroll
    for (int i = 0; i < KK; i++)
        w[i] = (lane < KK) ? __expf(__ldg(&trans[i * KK + lane])) : 0.0f;

    // ---- alpha init ----
    float a, M;
    if (c == 0) {
        float al = (lane < KK) ? (startT[lane] + emb[lane]) : -1e30f;
        M = al;
        #pragma unroll
        for (int o = 16; o; o >>= 1)
            M = fmaxf(M, __shfl_xor_sync(0xffffffffu, M, o));
        a = (lane < KK) ? __expf(al - M) : 0.0f;
    } else {
        a = (lane < KK) ? 1.0f : 0.0f;     // uniform warm-up start
        M = 0.0f;
    }
    float base = 0.0f;                      // chunk 0: absolute reference

    // tile schedule: chunk c owns tiles 4c..4c+3 (64 steps).
    // c>0: round 0 = warm-up (last 8 steps of tile 4c-1), rounds 1..4 owned.
    const int k0 = (c == 0) ? 0 : 4 * c - 1;
    const int nr = (c == 0) ? 4 : 5;

    load_tile(ebuf[wid][0], emb + (size_t)k0 * TILEF, lane);
    CP_COMMIT();
    load_tile(ebuf[wid][1], emb + (size_t)(k0 + 1) * TILEF, lane);
    CP_COMMIT();

    for (int j = 0; j < nr; j++) {
        CP_WAIT1();
        __syncwarp();
        const float* eb = ebuf[wid][j & 1];

        if (c > 0 && j == 0) {
            // warm-up: steps 8..15 of tile 4c-1, all in-mask (prefix)
            #pragma unroll
            for (int tt = WU; tt < TSTEPS; ++tt)
                STEP_ONCE(tt)
            // snapshot: base = log n(alpha at chunk start)
            float zs = a;
            #pragma unroll
            for (int o = 16; o; o >>= 1)
                zs += __shfl_xor_sync(0xffffffffu, zs, o);
            base = M + __logf(zs);
        } else {
            const int jm = (c > 0) ? j - 1 : j;      // owned-tile index 0..3
            unsigned mw = (mwords[jm >> 1] >> (16 * (jm & 1))) & 0xFFFFu;
            int tt0 = 0;
            if (c == 0 && jm == 0) { mw &= ~1u; tt0 = 1; }
            const int nst = __popc(mw);              // mask is a prefix
            if (nst == TSTEPS - tt0 && tt0 == 0) {
                #pragma unroll
                for (int tt = 0; tt < TSTEPS; ++tt)
                    STEP_ONCE(tt)
            } else {
                for (int tt = tt0; tt < tt0 + nst; ++tt)
                    STEP_ONCE(tt)
                if (nst < TSTEPS - tt0) {            // boundary tile: done
                    CP_WAIT0();
                    break;
                }
            }
        }

        if (j + 2 < nr)
            load_tile(ebuf[wid][j & 1], emb + (size_t)(k0 + j + 2) * TILEF, lane);
        CP_COMMIT();
    }

    // ---- chunk contribution ----
    float zterm = (lane < KK) ? (contains ? a * __expf(endT[lane]) : a) : 0.0f;
    #pragma unroll
    for (int o = 16; o; o >>= 1)
        zterm += __shfl_xor_sync(0xffffffffu, zterm, o);
    float fin = M + __logf(zterm);

    if (lane == 0)
        g_part2[gw] = (fin - base) - numv;
}

__global__ void reduce_kernel(float* __restrict__ out)
{
    __shared__ float sh[256];
    int t = threadIdx.x;
    float v = 0.0f;
    #pragma unroll
    for (int i = 0; i < (BB * CHUNKS) / 256; i++)
        v += g_part2[t + 256 * i];
    sh[t] = v;
    __syncthreads();
    #pragma unroll
    for (int s2 = 128; s2; s2 >>= 1) {
        if (t < s2) sh[t] += sh[t + s2];
        __syncthreads();
    }
    if (t == 0) out[0] = sh[0] * (1.0f / (float)BB);
}

extern "C" void kernel_launch(void* const* d_in, const int* in_sizes, int n_in,
                              void* d_out, int out_size)
{
    const float* em  = (const float*)d_in[0];
    const float* st  = (const float*)d_in[1];
    const float* en  = (const float*)d_in[2];
    const float* tr  = (const float*)d_in[3];
    const int*   lab = (const int*)d_in[4];
    const int*   att = (const int*)d_in[5];
    float* out = (float*)d_out;

    int copy = (out_size > in_sizes[0]) ? 1 : 0;

    crf_kernel<<<NSCAN_BLOCKS + NCOPY_BLOCKS, 256>>>(em, st, en, tr, lab, att, out, copy);
    reduce_kernel<<<1, 256>>>(out);
}

// round 16
// speedup vs baseline: 1.0393x; 1.0393x over previous
#include <cuda_runtime.h>

// Problem constants (B, S, K) = (512, 2048, 17)
#define BB 512
#define SS 2048
#define KK 17
#define SK (SS * KK)
#define CHUNKS 32
#define CL 64               // steps owned per chunk
#define WU 8                // warm-up steps
#define TSTEPS 16           // steps per emission tile
#define TILEF (TSTEPS * KK) // 272 floats per tile
#define SCAN_WPB 8
#define NCOPY_BLOCKS 512
#define NSCAN_BLOCKS ((BB * CHUNKS) / SCAN_WPB)   // 2048

__device__ float g_part2[BB * CHUNKS];   // per-(seq,chunk) loss contribution

__device__ __forceinline__ void cp16(void* smem, const void* gmem) {
    unsigned s = (unsigned)__cvta_generic_to_shared(smem);
    asm volatile("cp.async.cg.shared.global [%0], [%1], 16;\n" :: "r"(s), "l"(gmem));
}
#define CP_COMMIT() asm volatile("cp.async.commit_group;\n" ::: "memory")
#define CP_WAIT1()  asm volatile("cp.async.wait_group 1;\n" ::: "memory")
#define CP_WAIT0()  asm volatile("cp.async.wait_group 0;\n" ::: "memory")

// one 272-float tile (68 x 16B) global -> shared via cp.async
__device__ __forceinline__ void load_tile(float* dst, const float* src, int lane) {
    cp16(dst + lane * 4,        src + lane * 4);
    cp16(dst + (32 + lane) * 4, src + (32 + lane) * 4);
    if (lane < 4)
        cp16(dst + (64 + lane) * 4, src + (64 + lane) * 4);
}

// one unmasked forward step (all in-mask); renorm bookkeeping every 8 steps.
// NOTE: no __syncwarp — the warp is convergent here, and the STS->LDS pair on
// arow aliases (runtime lane index), so both the compiler and the in-order
// per-warp LSU path preserve the store->load dependency warp-wide.
#define STEP_ONCE(tt)                                                          \
    {                                                                          \
        float e = eb[(tt) * KK + lane];                                        \
        float gg = __expf(e);                                                  \
        arow[wid][lane] = a;                                                   \
        const float* ar = arow[wid];                                           \
        float4 v0 = *(const float4*)&ar[0];                                    \
        float4 v1 = *(const float4*)&ar[4];                                    \
        float4 v2 = *(const float4*)&ar[8];                                    \
        float4 v3 = *(const float4*)&ar[12];                                   \
        float  v16 = ar[16];                                                   \
        float s0 = v0.x * w[0];                                                \
        float s1 = v0.y * w[1];                                                \
        float s2 = v0.z * w[2];                                                \
        float s3 = v0.w * w[3];                                                \
        s0 = fmaf(v1.x, w[4],  s0);                                            \
        s1 = fmaf(v1.y, w[5],  s1);                                            \
        s2 = fmaf(v1.z, w[6],  s2);                                            \
        s3 = fmaf(v1.w, w[7],  s3);                                            \
        s0 = fmaf(v2.x, w[8],  s0);                                            \
        s1 = fmaf(v2.y, w[9],  s1);                                            \
        s2 = fmaf(v2.z, w[10], s2);                                            \
        s3 = fmaf(v2.w, w[11], s3);                                            \
        s0 = fmaf(v3.x, w[12], s0);                                            \
        s1 = fmaf(v3.y, w[13], s1);                                            \
        s2 = fmaf(v3.z, w[14], s2);                                            \
        s3 = fmaf(v3.w, w[15], s3);                                            \
        s0 = fmaf(v16,  w[16], s0);                                            \
        float s = (s0 + s1) + (s2 + s3);                                       \
        a = s * gg;                                                            \
        if (((tt) & 7) == 0) {                                                 \
            float m0 = fmaxf(fmaxf(v0.x, v0.y), fmaxf(v0.z, v0.w));            \
            float m1 = fmaxf(fmaxf(v1.x, v1.y), fmaxf(v1.z, v1.w));            \
            float m2 = fmaxf(fmaxf(v2.x, v2.y), fmaxf(v2.z, v2.w));            \
            float m3 = fmaxf(fmaxf(v3.x, v3.y), fmaxf(v3.z, v3.w));            \
            float mx = fmaxf(fmaxf(m0, m1), fmaxf(fmaxf(m2, m3), v16));        \
            int e2 = (__float_as_int(mx) >> 23) - 127;                         \
            float scale = __int_as_float((127 - e2) << 23);                    \
            a *= scale;                                                        \
            M += (float)e2 * 0.6931471805599453f;                              \
        }                                                                      \
    }

__global__ __launch_bounds__(256) void crf_kernel(
    const float* __restrict__ em,      // [B,S,K]
    const float* __restrict__ startT,  // [K]
    const float* __restrict__ endT,    // [K]
    const float* __restrict__ trans,   // [K,K]
    const int*   __restrict__ labels,  // [B,S]
    const int*   __restrict__ attn,    // [B,S]
    float* __restrict__ out,           // [0]=loss, [1..]=emissions copy
    int copy_emissions)
{
    // ======== copy blocks first: saturate DRAM, scan backfills ========
    if (blockIdx.x < NCOPY_BLOCKS) {
        if (!copy_emissions) return;
        const size_t base = (size_t)blockIdx.x * SK;
        const float4* s4 = (const float4*)(em + base);
        float* dst = out + 1 + base;           // dst+3 is 16B-aligned
        const int n4 = (SK - 4) / 4;           // 8703 aligned float4 stores
        for (int j = threadIdx.x; j < n4; j += 256) {
            float4 x = s4[j];
            float4 y = s4[j + 1];              // overlapping load: L1 hit
            *(float4*)(dst + 3 + 4 * j) = make_float4(x.w, y.x, y.y, y.z);
        }
        if (threadIdx.x == 0) {
            float4 x0 = s4[0];
            dst[0] = x0.x; dst[1] = x0.y; dst[2] = x0.z;
            dst[SK - 1] = em[base + SK - 1];
        }
        return;
    }

    // ======== scan blocks: 8 warps, each = one (sequence, chunk) ========
    const int tid  = threadIdx.x;
    const int wid  = tid >> 5;
    const int lane = tid & 31;
    const int gw   = (blockIdx.x - NCOPY_BLOCKS) * SCAN_WPB + wid;
    const int b    = gw / CHUNKS;
    const int c    = gw % CHUNKS;

    const float* emb = em + (size_t)b * SK;
    const int*   lab = labels + (size_t)b * SS;
    const int*   msk = attn   + (size_t)b * SS;

    __shared__ __align__(16) float ebuf[SCAN_WPB][2][TILEF];
    __shared__ __align__(16) float arow[SCAN_WPB][32];

    const int tbase = c * CL;

    // ---- early active check (scalar, uniform) + immediate tile prefetch ----
    // active: chunk has any owned step in-mask (mask is a prefix)
    const bool active = (c == 0) || ((msk[tbase] != 0) && (lab[tbase] >= 0));
    if (!active) {
        if (lane == 0) g_part2[gw] = 0.0f;
        return;
    }

    // tile schedule: chunk c owns tiles 4c..4c+3 (64 steps).
    // c>0: round 0 = warm-up (last 8 steps of tile 4c-1), rounds 1..4 owned.
    const int k0 = (c == 0) ? 0 : 4 * c - 1;
    const int nr = (c == 0) ? 4 : 5;

    // issue the first two tile loads NOW; prologue below hides their latency
    load_tile(ebuf[wid][0], emb + (size_t)k0 * TILEF, lane);
    CP_COMMIT();
    load_tile(ebuf[wid][1], emb + (size_t)(k0 + 1) * TILEF, lane);
    CP_COMMIT();

    // ---- phase 1: masks + numerator for steps t in [c*CL, (c+1)*CL) ----
    unsigned mwords[2];
    float numv = 0.0f;
    #pragma unroll
    for (int r = 0; r < 2; r++) {
        int t  = tbase + 32 * r + lane;
        int lt = lab[t];
        bool m = (msk[t] != 0) && (lt >= 0);
        mwords[r] = __ballot_sync(0xffffffffu, m);
        if (m && t > 0) {
            int lp  = lab[t - 1];
            int lpc = (lp < 0) ? 0 : lp;
            numv += __ldg(&trans[lpc * KK + lt]) + emb[t * KK + lt];
        }
    }
    #pragma unroll
    for (int o = 16; o; o >>= 1)
        numv += __shfl_xor_sync(0xffffffffu, numv, o);

    // does this chunk contain the global last masked index?
    bool mnext = false;
    if (c < CHUNKS - 1) {
        int t = (c + 1) * CL;
        mnext = (msk[t] != 0) && (lab[t] >= 0);
    }
    const bool contains = !mnext;

    if (contains) {   // numerator end term (uniform across lanes)
        int li;
        if (mwords[1]) li = tbase + 32 + (31 - __clz(mwords[1]));
        else           li = tbase +      (31 - __clz(mwords[0]));
        int ll = lab[li];
        numv += endT[(ll < 0) ? 0 : ll];
    }
    if (c == 0) {
        int l0  = lab[0];
        int l0c = (l0 < 0) ? 0 : l0;
        numv += startT[l0c] + emb[l0c];
    }

    // exp(transitions) column for this lane's state
    float w[KK];
    #pragma unroll
    for (int i = 0; i < KK; i++)
        w[i] = (lane < KK) ? __expf(__ldg(&trans[i * KK + lane])) : 0.0f;

    // ---- alpha init ----
    float a, M;
    if (c == 0) {
        float al = (lane < KK) ? (startT[lane] + emb[lane]) : -1e30f;
        M = al;
        #pragma unroll
        for (int o = 16; o; o >>= 1)
            M = fmaxf(M, __shfl_xor_sync(0xffffffffu, M, o));
        a = (lane < KK) ? __expf(al - M) : 0.0f;
    } else {
        a = (lane < KK) ? 1.0f : 0.0f;     // uniform warm-up start
        M = 0.0f;
    }
    float base = 0.0f;                      // chunk 0: absolute reference

    for (int j = 0; j < nr; j++) {
        CP_WAIT1();
        __syncwarp();
        const float* eb = ebuf[wid][j & 1];

        if (c > 0 && j == 0) {
            // warm-up: steps 8..15 of tile 4c-1, all in-mask (prefix)
            #pragma unroll
            for (int tt = WU; tt < TSTEPS; ++tt)
                STEP_ONCE(tt)
            // snapshot: base = log n(alpha at chunk start)
            float zs = a;
            #pragma unroll
            for (int o = 16; o; o >>= 1)
                zs += __shfl_xor_sync(0xffffffffu, zs, o);
            base = M + __logf(zs);
        } else {
            const int jm = (c > 0) ? j - 1 : j;      // owned-tile index 0..3
            unsigned mw = (mwords[jm >> 1] >> (16 * (jm & 1))) & 0xFFFFu;
            int tt0 = 0;
            if (c == 0 && jm == 0) { mw &= ~1u; tt0 = 1; }
            const int nst = __popc(mw);              // mask is a prefix
            if (nst == TSTEPS - tt0 && tt0 == 0) {
                #pragma unroll
                for (int tt = 0; tt < TSTEPS; ++tt)
                    STEP_ONCE(tt)
            } else {
                for (int tt = tt0; tt < tt0 + nst; ++tt)
                    STEP_ONCE(tt)
                if (nst < TSTEPS - tt0) {            // boundary tile: done
                    CP_WAIT0();
                    break;
                }
            }
        }

        if (j + 2 < nr)
            load_tile(ebuf[wid][j & 1], emb + (size_t)(k0 + j + 2) * TILEF, lane);
        CP_COMMIT();
    }

    // ---- chunk contribution ----
    float zterm = (lane < KK) ? (contains ? a * __expf(endT[lane]) : a) : 0.0f;
    #pragma unroll
    for (int o = 16; o; o >>= 1)
        zterm += __shfl_xor_sync(0xffffffffu, zterm, o);
    float fin = M + __logf(zterm);

    if (lane == 0)
        g_part2[gw] = (fin - base) - numv;
}

__global__ void reduce_kernel(float* __restrict__ out)
{
    __shared__ float sh[256];
    int t = threadIdx.x;
    float v = 0.0f;
    #pragma unroll
    for (int i = 0; i < (BB * CHUNKS) / 256; i++)
        v += g_part2[t + 256 * i];
    sh[t] = v;
    __syncthreads();
    #pragma unroll
    for (int s2 = 128; s2; s2 >>= 1) {
        if (t < s2) sh[t] += sh[t + s2];
        __syncthreads();
    }
    if (t == 0) out[0] = sh[0] * (1.0f / (float)BB);
}

extern "C" void kernel_launch(void* const* d_in, const int* in_sizes, int n_in,
                              void* d_out, int out_size)
{
    const float* em  = (const float*)d_in[0];
    const float* st  = (const float*)d_in[1];
    const float* en  = (const float*)d_in[2];
    const float* tr  = (const float*)d_in[3];
    const int*   lab = (const int*)d_in[4];
    const int*   att = (const int*)d_in[5];
    float* out = (float*)d_out;

    int copy = (out_size > in_sizes[0]) ? 1 : 0;

    crf_kernel<<<NCOPY_BLOCKS + NSCAN_BLOCKS, 256>>>(em, st, en, tr, lab, att, out, copy);
    reduce_kernel<<<1, 256>>>(out);
}

// round 17
// speedup vs baseline: 1.0734x; 1.0328x over previous
#include <cuda_runtime.h>

// Problem constants (B, S, K) = (512, 2048, 17)
#define BB 512
#define SS 2048
#define KK 17
#define SK (SS * KK)
#define CHUNKS 32
#define CL 64               // steps owned per chunk
#define WU 8                // warm-up steps
#define TSTEPS 16           // steps per emission tile
#define TILEF (TSTEPS * KK) // 272 floats per tile
#define SCAN_WPB 8
#define NCOPY_BLOCKS 512
#define NSCAN_BLOCKS ((BB * CHUNKS) / SCAN_WPB)   // 2048

__device__ float g_part2[BB * CHUNKS];   // per-(seq,chunk) loss contribution

__device__ __forceinline__ void cp16(void* smem, const void* gmem) {
    unsigned s = (unsigned)__cvta_generic_to_shared(smem);
    asm volatile("cp.async.cg.shared.global [%0], [%1], 16;\n" :: "r"(s), "l"(gmem));
}
#define CP_COMMIT() asm volatile("cp.async.commit_group;\n" ::: "memory")
#define CP_WAIT1()  asm volatile("cp.async.wait_group 1;\n" ::: "memory")
#define CP_WAIT0()  asm volatile("cp.async.wait_group 0;\n" ::: "memory")

// one 272-float tile (68 x 16B) global -> shared via cp.async
__device__ __forceinline__ void load_tile(float* dst, const float* src, int lane) {
    cp16(dst + lane * 4,        src + lane * 4);
    cp16(dst + (32 + lane) * 4, src + (32 + lane) * 4);
    if (lane < 4)
        cp16(dst + (64 + lane) * 4, src + (64 + lane) * 4);
}

// one unmasked forward step (all in-mask).
// Single 17-FMA accumulator chain (latency hidden by multi-warp issue).
// Renorm every 8 steps anchored on alpha_0's exponent (v0.x is the lane-0
// alpha, uniform across lanes and strictly positive; lane ratios are bounded
// by the Hilbert-metric diameter + emission drift, far within fp32 range).
// No __syncwarp: convergent warp; STS->LDS on arow aliases, so both compiler
// and the in-order per-warp LSU path preserve the dependency warp-wide.
#define STEP_ONCE(tt)                                                          \
    {                                                                          \
        float e = eb[(tt) * KK + lane];                                        \
        float gg = __expf(e);                                                  \
        arow[wid][lane] = a;                                                   \
        const float* ar = arow[wid];                                           \
        float4 v0 = *(const float4*)&ar[0];                                    \
        float4 v1 = *(const float4*)&ar[4];                                    \
        float4 v2 = *(const float4*)&ar[8];                                    \
        float4 v3 = *(const float4*)&ar[12];                                   \
        float  v16 = ar[16];                                                   \
        float s = v0.x * w[0];                                                 \
        s = fmaf(v0.y, w[1],  s);                                              \
        s = fmaf(v0.z, w[2],  s);                                              \
        s = fmaf(v0.w, w[3],  s);                                              \
        s = fmaf(v1.x, w[4],  s);                                              \
        s = fmaf(v1.y, w[5],  s);                                              \
        s = fmaf(v1.z, w[6],  s);                                              \
        s = fmaf(v1.w, w[7],  s);                                              \
        s = fmaf(v2.x, w[8],  s);                                              \
        s = fmaf(v2.y, w[9],  s);                                              \
        s = fmaf(v2.z, w[10], s);                                              \
        s = fmaf(v2.w, w[11], s);                                              \
        s = fmaf(v3.x, w[12], s);                                              \
        s = fmaf(v3.y, w[13], s);                                              \
        s = fmaf(v3.z, w[14], s);                                              \
        s = fmaf(v3.w, w[15], s);                                              \
        s = fmaf(v16,  w[16], s);                                              \
        a = s * gg;                                                            \
        if (((tt) & 7) == 0) {                                                 \
            int e2 = (__float_as_int(v0.x) >> 23) - 127;                       \
            a *= __int_as_float((127 - e2) << 23);                             \
            M += (float)e2 * 0.6931471805599453f;                              \
        }                                                                      \
    }

__global__ __launch_bounds__(256) void crf_kernel(
    const float* __restrict__ em,      // [B,S,K]
    const float* __restrict__ startT,  // [K]
    const float* __restrict__ endT,    // [K]
    const float* __restrict__ trans,   // [K,K]
    const int*   __restrict__ labels,  // [B,S]
    const int*   __restrict__ attn,    // [B,S]
    float* __restrict__ out,           // [0]=loss, [1..]=emissions copy
    int copy_emissions)
{
    // ======== copy blocks first: saturate DRAM, scan backfills ========
    if (blockIdx.x < NCOPY_BLOCKS) {
        if (!copy_emissions) return;
        const size_t base = (size_t)blockIdx.x * SK;
        const float4* s4 = (const float4*)(em + base);
        float* dst = out + 1 + base;           // dst+3 is 16B-aligned
        const int n4 = (SK - 4) / 4;           // 8703 aligned float4 stores
        for (int j = threadIdx.x; j < n4; j += 256) {
            float4 x = s4[j];
            float4 y = s4[j + 1];              // overlapping load: L1 hit
            *(float4*)(dst + 3 + 4 * j) = make_float4(x.w, y.x, y.y, y.z);
        }
        if (threadIdx.x == 0) {
            float4 x0 = s4[0];
            dst[0] = x0.x; dst[1] = x0.y; dst[2] = x0.z;
            dst[SK - 1] = em[base + SK - 1];
        }
        return;
    }

    // ======== scan blocks: 8 warps, each = one (sequence, chunk) ========
    const int tid  = threadIdx.x;
    const int wid  = tid >> 5;
    const int lane = tid & 31;
    const int gw   = (blockIdx.x - NCOPY_BLOCKS) * SCAN_WPB + wid;
    const int b    = gw / CHUNKS;
    const int c    = gw % CHUNKS;

    const float* emb = em + (size_t)b * SK;
    const int*   lab = labels + (size_t)b * SS;
    const int*   msk = attn   + (size_t)b * SS;

    __shared__ __align__(16) float ebuf[SCAN_WPB][2][TILEF];
    __shared__ __align__(16) float arow[SCAN_WPB][32];

    // ---- phase 1: masks + numerator for steps t in [c*CL, (c+1)*CL) ----
    const int tbase = c * CL;
    unsigned mwords[2];
    float numv = 0.0f;
    #pragma unroll
    for (int r = 0; r < 2; r++) {
        int t  = tbase + 32 * r + lane;
        int lt = lab[t];
        bool m = (msk[t] != 0) && (lt >= 0);
        mwords[r] = __ballot_sync(0xffffffffu, m);
        if (m && t > 0) {
            int lp  = lab[t - 1];
            int lpc = (lp < 0) ? 0 : lp;
            numv += __ldg(&trans[lpc * KK + lt]) + emb[t * KK + lt];
        }
    }
    #pragma unroll
    for (int o = 16; o; o >>= 1)
        numv += __shfl_xor_sync(0xffffffffu, numv, o);

    // active: chunk has any owned step in-mask (mask is a prefix)
    bool active = (c == 0) || ((mwords[0] & 1u) != 0);
    if (!active) {
        if (lane == 0) g_part2[gw] = 0.0f;
        return;
    }

    // does this chunk contain the global last masked index?
    bool mnext = false;
    if (c < CHUNKS - 1) {
        int t = (c + 1) * CL;
        mnext = (msk[t] != 0) && (lab[t] >= 0);
    }
    const bool contains = !mnext;

    if (contains) {   // numerator end term (uniform across lanes)
        int li;
        if (mwords[1]) li = tbase + 32 + (31 - __clz(mwords[1]));
        else           li = tbase +      (31 - __clz(mwords[0]));
        int ll = lab[li];
        numv += endT[(ll < 0) ? 0 : ll];
    }
    if (c == 0) {
        int l0  = lab[0];
        int l0c = (l0 < 0) ? 0 : l0;
        numv += startT[l0c] + emb[l0c];
    }

    // exp(transitions) column for this lane's state
    float w[KK];
    #pragma unroll
    for (int i = 0; i < KK; i++)
        w[i] = (lane < KK) ? __expf(__ldg(&trans[i * KK + lane])) : 0.0f;

    // ---- alpha init ----
    float a, M;
    if (c == 0) {
        float al = (lane < KK) ? (startT[lane] + emb[lane]) : -1e30f;
        M = al;
        #pragma unroll
        for (int o = 16; o; o >>= 1)
            M = fmaxf(M, __shfl_xor_sync(0xffffffffu, M, o));
        a = (lane < KK) ? __expf(al - M) : 0.0f;
    } else {
        a = (lane < KK) ? 1.0f : 0.0f;     // uniform warm-up start
        M = 0.0f;
    }
    float base = 0.0f;                      // chunk 0: absolute reference

    // tile schedule: chunk c owns tiles 4c..4c+3 (64 steps).
    // c>0: round 0 = warm-up (last 8 steps of tile 4c-1), rounds 1..4 owned.
    const int k0 = (c == 0) ? 0 : 4 * c - 1;
    const int nr = (c == 0) ? 4 : 5;

    load_tile(ebuf[wid][0], emb + (size_t)k0 * TILEF, lane);
    CP_COMMIT();
    load_tile(ebuf[wid][1], emb + (size_t)(k0 + 1) * TILEF, lane);
    CP_COMMIT();

    for (int j = 0; j < nr; j++) {
        CP_WAIT1();
        __syncwarp();
        const float* eb = ebuf[wid][j & 1];

        if (c > 0 && j == 0) {
            // warm-up: steps 8..15 of tile 4c-1, all in-mask (prefix)
            #pragma unroll
            for (int tt = WU; tt < TSTEPS; ++tt)
                STEP_ONCE(tt)
            // snapshot: base = log n(alpha at chunk start)
            float zs = a;
            #pragma unroll
            for (int o = 16; o; o >>= 1)
                zs += __shfl_xor_sync(0xffffffffu, zs, o);
            base = M + __logf(zs);
        } else {
            const int jm = (c > 0) ? j - 1 : j;      // owned-tile index 0..3
            unsigned mw = (mwords[jm >> 1] >> (16 * (jm & 1))) & 0xFFFFu;
            int tt0 = 0;
            if (c == 0 && jm == 0) { mw &= ~1u; tt0 = 1; }
            const int nst = __popc(mw);              // mask is a prefix
            if (nst == TSTEPS - tt0 && tt0 == 0) {
                #pragma unroll
                for (int tt = 0; tt < TSTEPS; ++tt)
                    STEP_ONCE(tt)
            } else {
                for (int tt = tt0; tt < tt0 + nst; ++tt)
                    STEP_ONCE(tt)
                if (nst < TSTEPS - tt0) {            // boundary tile: done
                    CP_WAIT0();
                    break;
                }
            }
        }

        if (j + 2 < nr)
            load_tile(ebuf[wid][j & 1], emb + (size_t)(k0 + j + 2) * TILEF, lane);
        CP_COMMIT();
    }

    // ---- chunk contribution ----
    float zterm = (lane < KK) ? (contains ? a * __expf(endT[lane]) : a) : 0.0f;
    #pragma unroll
    for (int o = 16; o; o >>= 1)
        zterm += __shfl_xor_sync(0xffffffffu, zterm, o);
    float fin = M + __logf(zterm);

    if (lane == 0)
        g_part2[gw] = (fin - base) - numv;
}

__global__ void reduce_kernel(float* __restrict__ out)
{
    __shared__ float sh[256];
    int t = threadIdx.x;
    float v = 0.0f;
    #pragma unroll
    for (int i = 0; i < (BB * CHUNKS) / 256; i++)
        v += g_part2[t + 256 * i];
    sh[t] = v;
    __syncthreads();
    #pragma unroll
    for (int s2 = 128; s2; s2 >>= 1) {
        if (t < s2) sh[t] += sh[t + s2];
        __syncthreads();
    }
    if (t == 0) out[0] = sh[0] * (1.0f / (float)BB);
}

extern "C" void kernel_launch(void* const* d_in, const int* in_sizes, int n_in,
                              void* d_out, int out_size)
{
    const float* em  = (const float*)d_in[0];
    const float* st  = (const float*)d_in[1];
    const float* en  = (const float*)d_in[2];
    const float* tr  = (const float*)d_in[3];
    const int*   lab = (const int*)d_in[4];
    const int*   att = (const int*)d_in[5];
    float* out = (float*)d_out;

    int copy = (out_size > in_sizes[0]) ? 1 : 0;

    crf_kernel<<<NCOPY_BLOCKS + NSCAN_BLOCKS, 256>>>(em, st, en, tr, lab, att, out, copy);
    reduce_kernel<<<1, 256>>>(out);
}